// round 8
// baseline (speedup 1.0000x reference)
#include <cuda_runtime.h>
#include <math.h>
#include <cstdint>

#define BB 256
#define SS 4096
#define HH 64
#define GG 192   // 3*H

// Scratch
__device__ float g_buf[(size_t)BB * SS * HH];      // 268 MB  layer activations
__device__ float g_xi [(size_t)BB * SS * GG];      // 805 MB  xi (includes b_ih), layout [b][t][row]
__device__ float g_scores[(size_t)BB * 4 * SS];    // 16 MB

__device__ __forceinline__ float sigmoidf_(float x) {
    return __fdividef(1.0f, 1.0f + __expf(-x));
}
__device__ __forceinline__ float tanhf_(float x) {
    x = fminf(fmaxf(x, -15.0f), 15.0f);
    float e = __expf(2.0f * x);
    return __fdividef(e - 1.0f, e + 1.0f);
}

// 64-dot, 8 accumulators (chain depth 8 FMA = 32 cyc)
__device__ __forceinline__ float dot64w_(const float* __restrict__ w, const float* sv) {
    const float4* hv = (const float4*)sv;
    float a0 = 0.f, a1 = 0.f, a2 = 0.f, a3 = 0.f;
    float a4 = 0.f, a5 = 0.f, a6 = 0.f, a7 = 0.f;
#pragma unroll
    for (int kk = 0; kk < 16; kk += 2) {
        float4 v0 = hv[kk], v1 = hv[kk + 1];
        a0 = fmaf(w[4 * kk + 0], v0.x, a0);
        a1 = fmaf(w[4 * kk + 1], v0.y, a1);
        a2 = fmaf(w[4 * kk + 2], v0.z, a2);
        a3 = fmaf(w[4 * kk + 3], v0.w, a3);
        a4 = fmaf(w[4 * kk + 4], v1.x, a4);
        a5 = fmaf(w[4 * kk + 5], v1.y, a5);
        a6 = fmaf(w[4 * kk + 6], v1.z, a6);
        a7 = fmaf(w[4 * kk + 7], v1.w, a7);
    }
    return ((a0 + a1) + (a2 + a3)) + ((a4 + a5) + (a6 + a7));
}

__device__ __forceinline__ float dot64_(const float* __restrict__ w, const float* sv) {
    const float4* hv = (const float4*)sv;
    float a0 = 0.f, a1 = 0.f, a2 = 0.f, a3 = 0.f;
#pragma unroll
    for (int kk = 0; kk < 16; kk++) {
        float4 v = hv[kk];
        a0 = fmaf(w[4 * kk + 0], v.x, a0);
        a1 = fmaf(w[4 * kk + 1], v.y, a1);
        a2 = fmaf(w[4 * kk + 2], v.z, a2);
        a3 = fmaf(w[4 * kk + 3], v.w, a3);
    }
    return (a0 + a1) + (a2 + a3);
}

// tf32 helpers
__device__ __forceinline__ uint32_t f2tf32_(float x) {
    uint32_t r;
    asm("cvt.rna.tf32.f32 %0, %1;" : "=r"(r) : "f"(x));
    return r;
}
__device__ __forceinline__ void mma_tf32_(float* c, const uint32_t* a, const uint32_t* b) {
    asm volatile("mma.sync.aligned.m16n8k8.row.col.f32.tf32.tf32.f32 "
        "{%0,%1,%2,%3},{%4,%5,%6,%7},{%8,%9},{%0,%1,%2,%3};"
        : "+f"(c[0]), "+f"(c[1]), "+f"(c[2]), "+f"(c[3])
        : "r"(a[0]), "r"(a[1]), "r"(a[2]), "r"(a[3]), "r"(b[0]), "r"(b[1]));
}

__global__ void warm_kernel() {
    if (threadIdx.x == 0) g_scores[blockIdx.x] = 0.0f;
}

// ---------------------------------------------------------------------------
// Triple-lane recurrence: 224 threads = 7 warps. Each warp owns 10 h-elements
// (warp 6: 4), 3 lanes per element: role 0 = r-row, 1 = z-row, 2 = n-row.
// Every active lane computes its gate-row h-dot (64 FMA). r,z sigmoids reach
// the n-lane by intra-warp shfl (no barrier). n-lane writes the new h into
// the OTHER h buffer -> ONE __syncthreads() per step.
// IS_L0: ai computed from scalar x; else from precomputed g_xi.
// ---------------------------------------------------------------------------
template <bool IS_L0>
__device__ __forceinline__ void rec_core(
    const float* __restrict__ whh, const float* __restrict__ bhh,
    const float* __restrict__ wih, const float* __restrict__ bih,
    const float* __restrict__ xin,    // IS_L0: x + b*SS
    const float* __restrict__ xibase, // !IS_L0: g_xi + b*SS*GG
    float* __restrict__ outp)
{
    __shared__ __align__(16) float sh[2][HH];

    const int tid = threadIdx.x;
    const int warp = tid >> 5, lane = tid & 31;
    const int tk = lane / 3, role = lane - tk * 3;
    const int k = warp * 10 + tk;
    const bool active = (lane < 30) && (k < HH);
    const uint32_t mask = (warp < 6) ? 0x3FFFFFFFu : 0x00000FFFu;
    const int rsrc = tk * 3, zsrc = tk * 3 + 1;
    const int row = role * HH + k;    // gate row (r/z/n block)

    float wh[HH];
    float bh = 0.f, wi = 0.f, bi = 0.f;
    const float* myxi = nullptr;
    if (active) {
#pragma unroll
        for (int j = 0; j < HH; j++) wh[j] = whh[row * HH + j];
        bh = bhh[row];
        if (IS_L0) { wi = wih[row]; bi = bih[row]; }
        else       myxi = xibase + row;
    }

    float xr[4] = {0.f, 0.f, 0.f, 0.f};
    if (active) {
#pragma unroll
        for (int i = 0; i < 4; i++)
            xr[i] = IS_L0 ? xin[i] : myxi[(size_t)i * GG];
    }
    if (tid < HH) { sh[0][tid] = 0.0f; sh[1][tid] = 0.0f; }
    __syncthreads();

    int p = 0;
    for (int t = 0; t < SS; t++) {
        if (active) {
            const float ah = dot64w_(wh, sh[p]) + bh;
            const float ai = IS_L0 ? fmaf(wi, xr[t & 3], bi) : xr[t & 3];
            const int tp = t + 4;
            if (tp < SS) xr[t & 3] = IS_L0 ? xin[tp] : myxi[(size_t)tp * GG];

            float val = 0.0f;
            if (role < 2) val = sigmoidf_(ai + ah);
            const float rv = __shfl_sync(mask, val, rsrc);
            const float zv = __shfl_sync(mask, val, zsrc);
            if (role == 2) {
                const float n = tanhf_(fmaf(rv, ah, ai));
                const float hp = sh[p][k];
                const float hn = fmaf(zv, hp - n, n);
                sh[1 - p][k] = hn;
                outp[(size_t)t * HH + k] = hn;
            }
        }
        __syncthreads();
        p ^= 1;
    }
}

__global__ __launch_bounds__(224, 2)
void rec0_kernel(const float* __restrict__ x,
                 const float* __restrict__ wih, const float* __restrict__ whh,
                 const float* __restrict__ bih, const float* __restrict__ bhh)
{
    const int b = blockIdx.x;
    rec_core<true>(whh, bhh, wih, bih,
                   x + (size_t)b * SS, nullptr,
                   g_buf + (size_t)b * SS * HH);
}

__global__ __launch_bounds__(224, 2)
void rec_kernel(const float* __restrict__ whh, const float* __restrict__ bhh)
{
    const int b = blockIdx.x;
    rec_core<false>(whh, bhh, nullptr, nullptr,
                    nullptr, g_xi + (size_t)b * SS * GG,
                    g_buf + (size_t)b * SS * HH);
}

// ---------------------------------------------------------------------------
// xi GEMM on mma.sync tf32 (hi/lo split, fp32 accumulate, 3-term).
// (unchanged from R7: measured 679 us, tensor=40.8%)
// ---------------------------------------------------------------------------
__global__ __launch_bounds__(512, 1)
void xi_gemm_mma(const float* __restrict__ wih, const float* __restrict__ bih)
{
    __shared__ __align__(16) float sA[128 * 68];   // 34.8 KB

    const int tid = threadIdx.x;
    const int wid = tid >> 5, lane = tid & 31;
    const int wm = wid & 3, wn = wid >> 2;         // 4 x 4 warp grid
    const int g = lane >> 2, q = lane & 3;
    const size_t row0 = (size_t)blockIdx.x * 128;

    {
        const float4* src = (const float4*)(g_buf + row0 * HH);
#pragma unroll
        for (int i = 0; i < 4; i++) {
            int idx = tid + i * 512;
            int rr = idx >> 4, c4 = idx & 15;
            float4 v = src[idx];
            *(float4*)(sA + rr * 68 + c4 * 4) = v;
        }
    }
    __syncthreads();

    float c[2][6][4] = {};

    for (int kt = 0; kt < 8; kt++) {
        uint32_t ah[2][4], al[2][4];
#pragma unroll
        for (int mt = 0; mt < 2; mt++) {
#pragma unroll
            for (int e = 0; e < 4; e++) {
                int row = wm * 32 + mt * 16 + g + (e & 1) * 8;
                int col = kt * 8 + q + (e >> 1) * 4;
                float v = sA[row * 68 + col];
                uint32_t hi = f2tf32_(v);
                ah[mt][e] = hi;
                al[mt][e] = f2tf32_(v - __uint_as_float(hi));
            }
        }
        uint32_t bh[6][2], bl[6][2];
#pragma unroll
        for (int nt = 0; nt < 6; nt++) {
#pragma unroll
            for (int e = 0; e < 2; e++) {
                int n = wn * 48 + nt * 8 + g;
                int k = kt * 8 + q + e * 4;
                float v = __ldg(&wih[n * 64 + k]);
                uint32_t hi = f2tf32_(v);
                bh[nt][e] = hi;
                bl[nt][e] = f2tf32_(v - __uint_as_float(hi));
            }
        }
#pragma unroll
        for (int mt = 0; mt < 2; mt++) {
#pragma unroll
            for (int nt = 0; nt < 6; nt++) {
                mma_tf32_(c[mt][nt], ah[mt], bh[nt]);
                mma_tf32_(c[mt][nt], al[mt], bh[nt]);
                mma_tf32_(c[mt][nt], ah[mt], bl[nt]);
            }
        }
    }

#pragma unroll
    for (int mt = 0; mt < 2; mt++) {
        const size_t row = row0 + wm * 32 + mt * 16 + g;
#pragma unroll
        for (int nt = 0; nt < 6; nt++) {
            const int col = wn * 48 + nt * 8 + q * 2;
            const float b0v = __ldg(&bih[col]);
            const float b1v = __ldg(&bih[col + 1]);
            *(float2*)(g_xi + row * GG + col) =
                make_float2(c[mt][nt][0] + b0v, c[mt][nt][1] + b1v);
            *(float2*)(g_xi + (row + 8) * GG + col) =
                make_float2(c[mt][nt][2] + b0v, c[mt][nt][3] + b1v);
        }
    }
}

// ---------------------------------------------------------------------------
// Attention + head (unchanged; known-good).
// ---------------------------------------------------------------------------
__global__ __launch_bounds__(256)
void attn_kernel(
    const float* __restrict__ in_proj_w, const float* __restrict__ in_proj_b,
    const float* __restrict__ out_proj_w, const float* __restrict__ out_proj_b,
    const float* __restrict__ fc_w, const float* __restrict__ fc_b,
    float* __restrict__ out)
{
    const int b = blockIdx.x;
    const int tid = threadIdx.x;

    __shared__ __align__(16) float shl[HH];
    __shared__ __align__(16) float sq[HH];
    __shared__ __align__(16) float sg[4][HH];
    __shared__ float sc[4];
    __shared__ float sred[4][256];
    __shared__ float sm4[4], sl4[4];
    __shared__ __align__(16) float stile[64][HH];
    __shared__ float sw[4][64];
    __shared__ float su[4][HH];
    __shared__ __align__(16) float sctx[HH];
    __shared__ float sao[HH];

    const float* mybuf = g_buf + (size_t)b * SS * HH;

    if (tid < HH) shl[tid] = mybuf[(size_t)(SS - 1) * HH + tid];
    __syncthreads();

    if (tid < HH) {
        float acc = in_proj_b[tid];
#pragma unroll
        for (int k = 0; k < HH; k++)
            acc = fmaf(in_proj_w[tid * HH + k], shl[k], acc);
        sq[tid] = acc;
    }
    __syncthreads();

    if (tid < HH) {
#pragma unroll
        for (int h = 0; h < 4; h++) {
            float acc = 0.0f;
#pragma unroll
            for (int d = 0; d < 16; d++)
                acc = fmaf(sq[h * 16 + d], in_proj_w[(HH + h * 16 + d) * HH + tid], acc);
            sg[h][tid] = acc * 0.25f;
        }
    }
    if (tid < 4) {
        float acc = 0.0f;
#pragma unroll
        for (int d = 0; d < 16; d++)
            acc = fmaf(sq[tid * 16 + d], in_proj_b[HH + tid * 16 + d], acc);
        sc[tid] = acc * 0.25f;
    }
    __syncthreads();

    float mloc[4] = {-1e30f, -1e30f, -1e30f, -1e30f};
    for (int s = tid; s < SS; s += 256) {
        const float4* ov = (const float4*)(mybuf + (size_t)s * HH);
        float4 o[16];
#pragma unroll
        for (int kk = 0; kk < 16; kk++) o[kk] = ov[kk];
#pragma unroll
        for (int h = 0; h < 4; h++) {
            const float4* gv = (const float4*)sg[h];
            float a0 = sc[h], a1 = 0.f, a2 = 0.f, a3 = 0.f;
#pragma unroll
            for (int kk = 0; kk < 16; kk++) {
                float4 g4 = gv[kk];
                a0 = fmaf(g4.x, o[kk].x, a0);
                a1 = fmaf(g4.y, o[kk].y, a1);
                a2 = fmaf(g4.z, o[kk].z, a2);
                a3 = fmaf(g4.w, o[kk].w, a3);
            }
            float sv = (a0 + a1) + (a2 + a3);
            g_scores[((size_t)(b * 4 + h)) * SS + s] = sv;
            mloc[h] = fmaxf(mloc[h], sv);
        }
    }
#pragma unroll
    for (int h = 0; h < 4; h++) sred[h][tid] = mloc[h];
    __syncthreads();
    if (tid < 4) {
        float m = -1e30f;
        for (int i = 0; i < 256; i++) m = fmaxf(m, sred[tid][i]);
        sm4[tid] = m;
    }
    __syncthreads();

    const int h = tid >> 6;
    const int e = tid & 63;
    const float mh = sm4[h];
    float uacc = 0.0f, lloc = 0.0f;

    for (int tile = 0; tile < SS / 64; tile++) {
        const int s0 = tile * 64;
        {
            float4* st4 = (float4*)stile;
            const float4* gv = (const float4*)(mybuf + (size_t)s0 * HH);
#pragma unroll
            for (int r = 0; r < 4; r++) {
                int idx = tid + r * 256;
                st4[idx] = gv[idx];
            }
        }
        {
            float w = __expf(g_scores[((size_t)(b * 4 + h)) * SS + s0 + e] - mh);
            sw[h][e] = w;
            lloc += w;
        }
        __syncthreads();
#pragma unroll
        for (int sp = 0; sp < 64; sp++)
            uacc = fmaf(sw[h][sp], stile[sp][e], uacc);
        __syncthreads();
    }

    ((float*)sred)[tid] = lloc;
    __syncthreads();
    if (tid < 4) {
        float l = 0.0f;
        for (int i = 0; i < 64; i++) l += ((float*)sred)[tid * 64 + i];
        sl4[tid] = l;
    }
    __syncthreads();

    su[h][e] = uacc / sl4[h];
    __syncthreads();

    if (tid < HH) {
        const int hh = tid >> 4;
        float acc = in_proj_b[128 + tid];
#pragma unroll
        for (int k = 0; k < HH; k++)
            acc = fmaf(in_proj_w[(128 + tid) * HH + k], su[hh][k], acc);
        sctx[tid] = acc;
    }
    __syncthreads();

    if (tid < HH) {
        float acc = out_proj_b[tid];
#pragma unroll
        for (int k = 0; k < HH; k++)
            acc = fmaf(out_proj_w[tid * HH + k], sctx[k], acc);
        sao[tid] = fc_w[tid] * acc;
    }
    __syncthreads();

    if (tid == 0) {
        float lg = fc_b[0];
        for (int i = 0; i < HH; i++) lg += sao[i];
        out[b] = 1.0f / (1.0f + __expf(-lg));
    }
}

// ---------------------------------------------------------------------------
extern "C" void kernel_launch(void* const* d_in, const int* in_sizes, int n_in,
                              void* d_out, int out_size)
{
    const float* x    = (const float*)d_in[0];
    const float* wih0 = (const float*)d_in[1];
    const float* whh0 = (const float*)d_in[2];
    const float* bih0 = (const float*)d_in[3];
    const float* bhh0 = (const float*)d_in[4];
    const float* wih1 = (const float*)d_in[5];
    const float* whh1 = (const float*)d_in[6];
    const float* bih1 = (const float*)d_in[7];
    const float* bhh1 = (const float*)d_in[8];
    const float* wih2 = (const float*)d_in[9];
    const float* whh2 = (const float*)d_in[10];
    const float* bih2 = (const float*)d_in[11];
    const float* bhh2 = (const float*)d_in[12];
    const float* ipw  = (const float*)d_in[13];
    const float* ipb  = (const float*)d_in[14];
    const float* opw  = (const float*)d_in[15];
    const float* opb  = (const float*)d_in[16];
    const float* fcw  = (const float*)d_in[17];
    const float* fcb  = (const float*)d_in[18];

    warm_kernel<<<1, 32>>>();                               // #1
    warm_kernel<<<1, 32>>>();                               // #2
    warm_kernel<<<1, 32>>>();                               // #3
    rec0_kernel<<<BB, 224>>>(x, wih0, whh0, bih0, bhh0);    // #4
    xi_gemm_mma<<<8192, 512>>>(wih1, bih1);                 // #5
    rec_kernel<<<BB, 224>>>(whh1, bhh1);                    // #6 <- profiled
    xi_gemm_mma<<<8192, 512>>>(wih2, bih2);                 // #7
    rec_kernel<<<BB, 224>>>(whh2, bhh2);                    // #8
    attn_kernel<<<BB, 256>>>(ipw, ipb, opw, opb, fcw, fcb, (float*)d_out);
}

// round 9
// speedup vs baseline: 1.1614x; 1.1614x over previous
#include <cuda_runtime.h>
#include <math.h>

#define BB 256
#define SS 4096
#define HH 64
#define GG 192   // 3*H

// Scratch
__device__ float g_buf[(size_t)BB * SS * HH];      // 268 MB  layer activations
__device__ float g_scores[(size_t)BB * 4 * SS];    // 16 MB

__device__ __forceinline__ float sigmoidf_(float x) {
    return 1.0f / (1.0f + __expf(-x));
}
__device__ __forceinline__ float tanhf_(float x) {
    x = fminf(fmaxf(x, -15.0f), 15.0f);
    float e = __expf(2.0f * x);
    return (e - 1.0f) / (e + 1.0f);
}

// group barrier: 192 threads (6 whole warps) of one batch-group
__device__ __forceinline__ void gsync_(int id) {
    asm volatile("bar.sync %0, %1;" :: "r"(id), "r"(192) : "memory");
}

__global__ void warm_kernel() {
    if (threadIdx.x == 0) g_scores[blockIdx.x] = 0.0f;
}

// ---------------------------------------------------------------------------
// GRU layer (R1-proven structure), group-scoped: j in [0,192), barrier id
// selects this group's named barrier. Thread j owns gate row j; weights in
// registers; h lives in group-private smem.
// ---------------------------------------------------------------------------
template <bool FIRST>
__device__ void gru_layer(
    int j, int bar,
    const float* __restrict__ wih, const float* __restrict__ whh,
    const float* __restrict__ bih, const float* __restrict__ bhh,
    const float* __restrict__ inp,   // FIRST: x + b*SS (scalar/step); else buf
    float* __restrict__ outp,        // buf (may alias inp; read t+2 < write t)
    float* sh, float (*sx)[HH], float* srz)
{
    constexpr int IN = FIRST ? 1 : HH;

    float wi[IN];
    float wh[HH];
#pragma unroll
    for (int k = 0; k < HH; k++) wh[k] = whh[j * HH + k];
#pragma unroll
    for (int k = 0; k < IN; k++) wi[k] = wih[j * IN + k];
    const float bi = bih[j];
    const float bh = bhh[j];

    if (j < HH) sh[j] = 0.0f;
    float xreg = 0.0f;
    if (j < IN) {
        sx[0][j] = inp[j];                 // t = 0
        xreg     = inp[(size_t)IN + j];    // t = 1
    }
    gsync_(bar);

    for (int t = 0; t < SS; t++) {
        const int cur = t & 1;
        // ---- phase A: input dot + hidden dot ----
        float ai;
        if (FIRST) {
            ai = fmaf(wi[0], sx[cur][0], bi);
        } else {
            const float4* xv = (const float4*)sx[cur];
            float a0 = bi, a1 = 0.f, a2 = 0.f, a3 = 0.f;
#pragma unroll
            for (int kk = 0; kk < 16; kk++) {
                float4 v = xv[kk];
                a0 = fmaf(wi[4 * kk + 0], v.x, a0);
                a1 = fmaf(wi[4 * kk + 1], v.y, a1);
                a2 = fmaf(wi[4 * kk + 2], v.z, a2);
                a3 = fmaf(wi[4 * kk + 3], v.w, a3);
            }
            ai = (a0 + a1) + (a2 + a3);
        }
        float ah;
        {
            const float4* hv = (const float4*)sh;
            float a0 = bh, a1 = 0.f, a2 = 0.f, a3 = 0.f;
#pragma unroll
            for (int kk = 0; kk < 16; kk++) {
                float4 v = hv[kk];
                a0 = fmaf(wh[4 * kk + 0], v.x, a0);
                a1 = fmaf(wh[4 * kk + 1], v.y, a1);
                a2 = fmaf(wh[4 * kk + 2], v.z, a2);
                a3 = fmaf(wh[4 * kk + 3], v.w, a3);
            }
            ah = (a0 + a1) + (a2 + a3);
        }
        if (j < 128) srz[j] = sigmoidf_(ai + ah);   // r rows [0,64), z rows [64,128)
        gsync_(bar);

        // ---- phase B ----
        if (j >= 128) {
            const int k = j - 128;
            float r = srz[k];
            float z = srz[64 + k];
            float n = tanhf_(fmaf(r, ah, ai));      // tanh(xn + r*hn)
            float hp = sh[k];
            float hn = fmaf(z, hp - n, n);          // (1-z)*n + z*h
            sh[k] = hn;
            outp[(size_t)t * HH + k] = hn;
        } else if (j < IN) {
            sx[1 - cur][j] = xreg;                  // stage x_{t+1}
            xreg = (t + 2 < SS) ? inp[(size_t)(t + 2) * IN + j] : 0.0f;
        }
        gsync_(bar);
    }
}

// ---------------------------------------------------------------------------
// Fused 3-layer GRU, TWO batch elements per CTA.
// Group g = warps [6g, 6g+6) handles batch 2*blockIdx.x + g with its own
// named barrier and private smem -> the two serial chains interleave on one
// SM without coupling. grid = 128 -> single wave.
// ---------------------------------------------------------------------------
__global__ __launch_bounds__(384, 1)
void gru_kernel(
    const float* __restrict__ x,
    const float* __restrict__ wih0, const float* __restrict__ whh0,
    const float* __restrict__ bih0, const float* __restrict__ bhh0,
    const float* __restrict__ wih1, const float* __restrict__ whh1,
    const float* __restrict__ bih1, const float* __restrict__ bhh1,
    const float* __restrict__ wih2, const float* __restrict__ whh2,
    const float* __restrict__ bih2, const float* __restrict__ bhh2)
{
    __shared__ __align__(16) float sh[2][HH];
    __shared__ __align__(16) float sx[2][2][HH];   // [group][buf][k]
    __shared__ float srz[2][128];

    const int group = threadIdx.x / 192;
    const int j = threadIdx.x % 192;
    const int bar = group + 1;                     // named barriers 1,2
    const int b = 2 * blockIdx.x + group;

    float* buf = g_buf + (size_t)b * SS * HH;
    float* shg = sh[group];
    float (*sxg)[HH] = sx[group];
    float* srzg = srz[group];

    gru_layer<true >(j, bar, wih0, whh0, bih0, bhh0,
                     x + (size_t)b * SS, buf, shg, sxg, srzg);
    gsync_(bar);
    gru_layer<false>(j, bar, wih1, whh1, bih1, bhh1, buf, buf, shg, sxg, srzg);
    gsync_(bar);
    gru_layer<false>(j, bar, wih2, whh2, bih2, bhh2, buf, buf, shg, sxg, srzg);
}

// ---------------------------------------------------------------------------
// Attention + head (unchanged; known-good).
// ---------------------------------------------------------------------------
__global__ __launch_bounds__(256)
void attn_kernel(
    const float* __restrict__ in_proj_w, const float* __restrict__ in_proj_b,
    const float* __restrict__ out_proj_w, const float* __restrict__ out_proj_b,
    const float* __restrict__ fc_w, const float* __restrict__ fc_b,
    float* __restrict__ out)
{
    const int b = blockIdx.x;
    const int tid = threadIdx.x;

    __shared__ __align__(16) float shl[HH];
    __shared__ __align__(16) float sq[HH];
    __shared__ __align__(16) float sg[4][HH];
    __shared__ float sc[4];
    __shared__ float sred[4][256];
    __shared__ float sm4[4], sl4[4];
    __shared__ __align__(16) float stile[64][HH];
    __shared__ float sw[4][64];
    __shared__ float su[4][HH];
    __shared__ __align__(16) float sctx[HH];
    __shared__ float sao[HH];

    const float* mybuf = g_buf + (size_t)b * SS * HH;

    if (tid < HH) shl[tid] = mybuf[(size_t)(SS - 1) * HH + tid];
    __syncthreads();

    if (tid < HH) {
        float acc = in_proj_b[tid];
#pragma unroll
        for (int k = 0; k < HH; k++)
            acc = fmaf(in_proj_w[tid * HH + k], shl[k], acc);
        sq[tid] = acc;
    }
    __syncthreads();

    if (tid < HH) {
#pragma unroll
        for (int h = 0; h < 4; h++) {
            float acc = 0.0f;
#pragma unroll
            for (int d = 0; d < 16; d++)
                acc = fmaf(sq[h * 16 + d], in_proj_w[(HH + h * 16 + d) * HH + tid], acc);
            sg[h][tid] = acc * 0.25f;
        }
    }
    if (tid < 4) {
        float acc = 0.0f;
#pragma unroll
        for (int d = 0; d < 16; d++)
            acc = fmaf(sq[tid * 16 + d], in_proj_b[HH + tid * 16 + d], acc);
        sc[tid] = acc * 0.25f;
    }
    __syncthreads();

    float mloc[4] = {-1e30f, -1e30f, -1e30f, -1e30f};
    for (int s = tid; s < SS; s += 256) {
        const float4* ov = (const float4*)(mybuf + (size_t)s * HH);
        float4 o[16];
#pragma unroll
        for (int kk = 0; kk < 16; kk++) o[kk] = ov[kk];
#pragma unroll
        for (int h = 0; h < 4; h++) {
            const float4* gv = (const float4*)sg[h];
            float a0 = sc[h], a1 = 0.f, a2 = 0.f, a3 = 0.f;
#pragma unroll
            for (int kk = 0; kk < 16; kk++) {
                float4 g4 = gv[kk];
                a0 = fmaf(g4.x, o[kk].x, a0);
                a1 = fmaf(g4.y, o[kk].y, a1);
                a2 = fmaf(g4.z, o[kk].z, a2);
                a3 = fmaf(g4.w, o[kk].w, a3);
            }
            float sv = (a0 + a1) + (a2 + a3);
            g_scores[((size_t)(b * 4 + h)) * SS + s] = sv;
            mloc[h] = fmaxf(mloc[h], sv);
        }
    }
#pragma unroll
    for (int h = 0; h < 4; h++) sred[h][tid] = mloc[h];
    __syncthreads();
    if (tid < 4) {
        float m = -1e30f;
        for (int i = 0; i < 256; i++) m = fmaxf(m, sred[tid][i]);
        sm4[tid] = m;
    }
    __syncthreads();

    const int h = tid >> 6;
    const int e = tid & 63;
    const float mh = sm4[h];
    float uacc = 0.0f, lloc = 0.0f;

    for (int tile = 0; tile < SS / 64; tile++) {
        const int s0 = tile * 64;
        {
            float4* st4 = (float4*)stile;
            const float4* gv = (const float4*)(mybuf + (size_t)s0 * HH);
#pragma unroll
            for (int r = 0; r < 4; r++) {
                int idx = tid + r * 256;
                st4[idx] = gv[idx];
            }
        }
        {
            float w = __expf(g_scores[((size_t)(b * 4 + h)) * SS + s0 + e] - mh);
            sw[h][e] = w;
            lloc += w;
        }
        __syncthreads();
#pragma unroll
        for (int sp = 0; sp < 64; sp++)
            uacc = fmaf(sw[h][sp], stile[sp][e], uacc);
        __syncthreads();
    }

    ((float*)sred)[tid] = lloc;
    __syncthreads();
    if (tid < 4) {
        float l = 0.0f;
        for (int i = 0; i < 64; i++) l += ((float*)sred)[tid * 64 + i];
        sl4[tid] = l;
    }
    __syncthreads();

    su[h][e] = uacc / sl4[h];
    __syncthreads();

    if (tid < HH) {
        const int hh = tid >> 4;
        float acc = in_proj_b[128 + tid];
#pragma unroll
        for (int k = 0; k < HH; k++)
            acc = fmaf(in_proj_w[(128 + tid) * HH + k], su[hh][k], acc);
        sctx[tid] = acc;
    }
    __syncthreads();

    if (tid < HH) {
        float acc = out_proj_b[tid];
#pragma unroll
        for (int k = 0; k < HH; k++)
            acc = fmaf(out_proj_w[tid * HH + k], sctx[k], acc);
        sao[tid] = fc_w[tid] * acc;
    }
    __syncthreads();

    if (tid == 0) {
        float lg = fc_b[0];
        for (int i = 0; i < HH; i++) lg += sao[i];
        out[b] = 1.0f / (1.0f + __expf(-lg));
    }
}

// ---------------------------------------------------------------------------
extern "C" void kernel_launch(void* const* d_in, const int* in_sizes, int n_in,
                              void* d_out, int out_size)
{
    const float* x    = (const float*)d_in[0];
    const float* wih0 = (const float*)d_in[1];
    const float* whh0 = (const float*)d_in[2];
    const float* bih0 = (const float*)d_in[3];
    const float* bhh0 = (const float*)d_in[4];
    const float* wih1 = (const float*)d_in[5];
    const float* whh1 = (const float*)d_in[6];
    const float* bih1 = (const float*)d_in[7];
    const float* bhh1 = (const float*)d_in[8];
    const float* wih2 = (const float*)d_in[9];
    const float* whh2 = (const float*)d_in[10];
    const float* bih2 = (const float*)d_in[11];
    const float* bhh2 = (const float*)d_in[12];
    const float* ipw  = (const float*)d_in[13];
    const float* ipb  = (const float*)d_in[14];
    const float* opw  = (const float*)d_in[15];
    const float* opb  = (const float*)d_in[16];
    const float* fcw  = (const float*)d_in[17];
    const float* fcb  = (const float*)d_in[18];

    warm_kernel<<<1, 32>>>();                                // #1
    warm_kernel<<<1, 32>>>();                                // #2
    warm_kernel<<<1, 32>>>();                                // #3
    gru_kernel<<<BB / 2, 384>>>(x, wih0, whh0, bih0, bhh0,   // #4 <- profiled
                                wih1, whh1, bih1, bhh1,
                                wih2, whh2, bih2, bhh2);
    attn_kernel<<<BB, 256>>>(ipw, ipb, opw, opb, fcw, fcb, (float*)d_out);
}